// round 15
// baseline (speedup 1.0000x reference)
#include <cuda_runtime.h>
#include <cuda_bf16.h>
#include <cuda_fp16.h>
#include <math.h>
#include <stdint.h>

#define S_LEN   512
#define NBATCH  128
#define IN_DIM  512
#define HID     1024
#define GDIM    4096   // interleaved: col g -> gate g&3, unit g>>2
#define NOUT    4

// phase-1 tiling: 128x128 tiles, BK=64, 3-stage cp.async (R11-proven)
#define BM 128
#define BN 128
#define BKP 64
#define P1TH 256
#define P1STG_B 32768
#define P1DYN (3 * P1STG_B)

// recurrence: 128 CTAs = 2 row-halves x 64 col-tiles, each 64x64xK
// 8 warps = 2(m) x 2(n) x 2(k-split)
#define PGRID 128
#define PTH 256
#define NCH 4                    // K chunks of 256
#define CHB 32768                // chunk: 64 rows x 512B
#define WB  131072               // W: 64 gate-cols x 2048B
#define OFF_W 0
#define OFF_A WB
#define DYN_B (WB + 3 * CHB)     // 229376

__device__ __half g_xp[(size_t)S_LEN * NBATCH * GDIM];   // x_proj (+bias), fp16
__device__ __half g_xh[(size_t)S_LEN * NBATCH * IN_DIM]; // inputs fp16
__device__ __half g_wih[(size_t)GDIM * IN_DIM];          // gathered W_ih fp16
__device__ float  g_bias[GDIM];                          // gathered b_ih+b_hh
__device__ __half g_hh[2][NBATCH * HID];                 // hidden fp16, dbl-buffered
__device__ int g_flag[PGRID * 32];                       // per-CTA step flag, 1 line each

__device__ __forceinline__ unsigned su32(const void* p){
    return (unsigned)__cvta_generic_to_shared(p);
}
__device__ __forceinline__ float fsig(float x){
    float e, r;
    asm("ex2.approx.f32 %0, %1;" : "=f"(e) : "f"(-x * 1.4426950408889634f));
    asm("rcp.approx.f32 %0, %1;" : "=f"(r) : "f"(1.0f + e));
    return r;
}
__device__ __forceinline__ float ftanh_(float x){
    float r;
    asm("tanh.approx.f32 %0, %1;" : "=f"(r) : "f"(x));
    return r;
}
__device__ __forceinline__ void cpasync16(unsigned saddr, const void* g){
    asm volatile("cp.async.cg.shared.global [%0], [%1], 16;" :: "r"(saddr), "l"(g));
}
#define CP_COMMIT() asm volatile("cp.async.commit_group;")
#define CP_WAIT(n)  asm volatile("cp.async.wait_group %0;" :: "n"(n))

__device__ __forceinline__ void ldmx4(unsigned* r, unsigned addr){
    asm volatile("ldmatrix.sync.aligned.m8n8.x4.shared.b16 {%0,%1,%2,%3}, [%4];"
        : "=r"(r[0]), "=r"(r[1]), "=r"(r[2]), "=r"(r[3]) : "r"(addr));
}
__device__ __forceinline__ void mma_f16(float* d, const unsigned* a, const unsigned* b){
    asm volatile("mma.sync.aligned.m16n8k16.row.col.f32.f16.f16.f32 "
        "{%0,%1,%2,%3},{%4,%5,%6,%7},{%8,%9},{%0,%1,%2,%3};"
        : "+f"(d[0]), "+f"(d[1]), "+f"(d[2]), "+f"(d[3])
        : "r"(a[0]), "r"(a[1]), "r"(a[2]), "r"(a[3]), "r"(b[0]), "r"(b[1]));
}

// all-warp redundant poll: chunk ch needs col-tiles [16ch,16ch+16) at flag >= tgt
__device__ __forceinline__ void flag_poll16(int ch, int tgt, int half, int lane){
    if (lane < 16){
        const volatile int* f = &g_flag[(((ch << 4) + lane) * 2 + half) * 32];
        while (*f < tgt) __nanosleep(64);
    }
    __syncwarp();
}

// ---------------- conversion pre-kernels ----------------
__global__ void cvt_inputs(const float* __restrict__ in){
    size_t i = (size_t)(blockIdx.x * blockDim.x + threadIdx.x) * 8;
    if (i < (size_t)S_LEN * NBATCH * IN_DIM){
        float4 v0 = *reinterpret_cast<const float4*>(in + i);
        float4 v1 = *reinterpret_cast<const float4*>(in + i + 4);
        __half2* d = reinterpret_cast<__half2*>(&g_xh[i]);
        d[0] = __floats2half2_rn(v0.x, v0.y);
        d[1] = __floats2half2_rn(v0.z, v0.w);
        d[2] = __floats2half2_rn(v1.x, v1.y);
        d[3] = __floats2half2_rn(v1.z, v1.w);
    }
}
__global__ void cvt_wih(const float* __restrict__ W_ih,
                        const float* __restrict__ b_ih, const float* __restrict__ b_hh,
                        const float* __restrict__ h0){
    int idx = blockIdx.x * blockDim.x + threadIdx.x;
    if (idx < GDIM * (IN_DIM / 4)){
        int g = idx >> 7;
        int c = (idx & 127) * 4;
        int r = (g & 3) * HID + (g >> 2);
        float4 v = *reinterpret_cast<const float4*>(W_ih + (size_t)r * IN_DIM + c);
        __half2* d = reinterpret_cast<__half2*>(&g_wih[(size_t)g * IN_DIM + c]);
        d[0] = __floats2half2_rn(v.x, v.y);
        d[1] = __floats2half2_rn(v.z, v.w);
        if (c == 0) g_bias[g] = b_ih[r] + b_hh[r];
    }
    if (idx < NBATCH * HID) g_hh[0][idx] = __float2half_rn(h0[idx]);
    if (idx < PGRID) g_flag[idx * 32] = 0;
}

// ---------------- phase 1: x_proj 128x128, 3-stage cp.async (R11-proven) ----------------
__global__ __launch_bounds__(P1TH)
void xproj_gemm()
{
    extern __shared__ __align__(1024) char p1s[];
    const int tid = threadIdx.x, lane = tid & 31, wid = tid >> 5;
    const int warp_m = wid & 3;
    const int warp_n = wid >> 2;
    const int m0 = blockIdx.y * BM, n0 = blockIdx.x * BN;
    const unsigned sbase = su32(p1s);

    float acc[2][4][2][4];
    #pragma unroll
    for (int a = 0; a < 2; a++)
        #pragma unroll
        for (int b = 0; b < 4; b++)
            #pragma unroll
            for (int c = 0; c < 2; c++)
                #pragma unroll
                for (int d = 0; d < 4; d++) acc[a][b][c][d] = 0.0f;

    int pr[8], pc[8], ppart[8];
    const __half* gsrc[8];
    #pragma unroll
    for (int i = 0; i < 8; i++){
        int idx = tid + i * P1TH;
        ppart[i] = idx >> 10;
        int w = idx & 1023;
        pr[i] = w >> 3;
        pc[i] = w & 7;
        gsrc[i] = ppart[i] ? (g_wih + (size_t)(n0 + pr[i]) * IN_DIM + pc[i] * 8)
                           : (g_xh  + (size_t)(m0 + pr[i]) * IN_DIM + pc[i] * 8);
    }

    #pragma unroll
    for (int st = 0; st < 2; st++){
        #pragma unroll
        for (int i = 0; i < 8; i++){
            unsigned dst = sbase + st * P1STG_B + ppart[i] * 16384
                         + pr[i] * 128 + ((pc[i] ^ (pr[i] & 7)) << 4);
            cpasync16(dst, gsrc[i] + st * BKP);
        }
        CP_COMMIT();
    }

    const int KIT = IN_DIM / BKP;
    for (int kt = 0; kt < KIT; kt++){
        if (kt + 1 < KIT) CP_WAIT(1); else CP_WAIT(0);
        __syncthreads();

        if (kt + 2 < KIT){
            int st = (kt + 2) % 3;
            #pragma unroll
            for (int i = 0; i < 8; i++){
                unsigned dst = sbase + st * P1STG_B + ppart[i] * 16384
                             + pr[i] * 128 + ((pc[i] ^ (pr[i] & 7)) << 4);
                cpasync16(dst, gsrc[i] + (kt + 2) * BKP);
            }
            CP_COMMIT();
        }

        const unsigned ab = sbase + (kt % 3) * P1STG_B;
        const unsigned bb = ab + 16384;
        #pragma unroll
        for (int kk = 0; kk < 4; kk++){
            const int lrow = lane & 15;
            const int cc = (kk * 16 + ((lane >> 4) << 3)) >> 3;
            unsigned ah[2][4];
            #pragma unroll
            for (int mt = 0; mt < 2; mt++){
                int r = warp_m * 32 + mt * 16 + lrow;
                ldmx4(ah[mt], ab + r * 128 + ((cc ^ (r & 7)) << 4));
            }
            #pragma unroll
            for (int nb = 0; nb < 4; nb++){
                int r = warp_n * 64 + nb * 16 + lrow;
                unsigned t4[4], b[2][2];
                ldmx4(t4, bb + r * 128 + ((cc ^ (r & 7)) << 4));
                b[0][0] = t4[0]; b[1][0] = t4[1]; b[0][1] = t4[2]; b[1][1] = t4[3];
                #pragma unroll
                for (int mt = 0; mt < 2; mt++)
                    #pragma unroll
                    for (int nt = 0; nt < 2; nt++)
                        mma_f16(acc[mt][nb][nt], ah[mt], b[nt]);
            }
        }
    }

    #pragma unroll
    for (int mt = 0; mt < 2; mt++)
        #pragma unroll
        for (int nb = 0; nb < 4; nb++)
            #pragma unroll
            for (int nt = 0; nt < 2; nt++)
                #pragma unroll
                for (int pp = 0; pp < 2; pp++){
                    int row = m0 + warp_m * 32 + mt * 16 + (lane >> 2) + 8 * pp;
                    int col = n0 + warp_n * 64 + nb * 16 + nt * 8 + 2 * (lane & 3);
                    float v0 = acc[mt][nb][nt][2 * pp]     + g_bias[col];
                    float v1 = acc[mt][nb][nt][2 * pp + 1] + g_bias[col + 1];
                    *reinterpret_cast<__half2*>(&g_xp[(size_t)row * GDIM + col]) =
                        __floats2half2_rn(v0, v1);
                }
}

// ---------------- persistent recurrence (8 warps, lean sync skeleton) ----------------
__device__ __forceinline__ void load_chunk(unsigned abase_st, const __half* hsrc,
                                           int m0, int kt, int tid){
    #pragma unroll
    for (int i = 0; i < 8; i++){
        int u = tid + i * PTH;
        int r = u >> 5;
        int c16 = u & 31;
        const __half* src = hsrc + (size_t)(m0 + r) * HID + kt * 256 + c16 * 8;
        unsigned dst = abase_st + r * 512 + ((((c16 ^ r) & 7) | (c16 & 24)) << 4);
        cpasync16(dst, src);
    }
}

__global__ __launch_bounds__(PTH, 1)
void lstm_rec(const float* __restrict__ W_hh, const float* __restrict__ c0)
{
    extern __shared__ __align__(1024) char dyn[];
    const int tid  = threadIdx.x;
    const int lane = tid & 31;
    const int wid  = tid >> 5;
    const int warp_m = wid & 1;
    const int warp_n = (wid >> 1) & 1;
    const int warp_k = wid >> 2;
    const int half = blockIdx.x & 1;
    const int m0 = half * 64;
    const int n0 = (blockIdx.x >> 1) * 64;
    const int myflag = blockIdx.x * 32;
    const unsigned wbase = su32(dyn + OFF_W);
    const unsigned abase = su32(dyn + OFF_A);

    for (int idx = tid; idx < 64 * (HID / 8); idx += PTH){
        int j  = idx >> 7;
        int c8 = idx & 127;
        int c  = c8 * 8;
        int g  = n0 + j;
        const float* src = W_hh + (size_t)((g & 3) * HID + (g >> 2)) * HID + c;
        float4 v0 = *reinterpret_cast<const float4*>(src);
        float4 v1 = *reinterpret_cast<const float4*>(src + 4);
        int sc = (c8 & ~7) | ((c8 ^ j) & 7);
        __half2* d = reinterpret_cast<__half2*>(dyn + OFF_W + j * 2048 + (sc << 4));
        d[0] = __floats2half2_rn(v0.x, v0.y);
        d[1] = __floats2half2_rn(v0.z, v0.w);
        d[2] = __floats2half2_rn(v1.x, v1.y);
        d[3] = __floats2half2_rn(v1.z, v1.w);
    }

    // epilogue ownership: 256 threads, each 4 consecutive units of one row
    const int erow = tid >> 2;
    const int q    = tid & 3;
    const int grow = m0 + erow;
    const int ub   = (n0 >> 2) + q * 4;
    float creg[4];
    #pragma unroll
    for (int u = 0; u < 4; u++) creg[u] = c0[grow * HID + ub + u];
    __syncthreads();

    for (int s = 0; s < S_LEN; s++){
        const __half* hsrc = g_hh[s & 1];

        const __half* xpr = g_xp + ((size_t)s * NBATCH + grow) * GDIM + n0 + q * 16;
        uint4 xpk[2];
        xpk[0] = *reinterpret_cast<const uint4*>(xpr);
        xpk[1] = *reinterpret_cast<const uint4*>(xpr + 8);

        float acc[2][4][4];
        #pragma unroll
        for (int a = 0; a < 2; a++)
            #pragma unroll
            for (int b = 0; b < 4; b++)
                #pragma unroll
                for (int k = 0; k < 4; k++) acc[a][b][k] = 0.0f;

        // all-warp redundant poll for chunk 0+1 producers (col-tiles 0..31, this half)
        if (lane < 32){
            const volatile int* f = &g_flag[(lane * 2 + half) * 32];
            while (*f < s) __nanosleep(64);
        }
        __syncwarp();
        // WAR: stage0 (gates) reads finished before the pre-publish sync last step;
        // stage1's chunk-1 reads finished before S_2 last step.
        load_chunk(abase + 0 * CHB, hsrc, m0, 0, tid); CP_COMMIT();
        load_chunk(abase + 1 * CHB, hsrc, m0, 1, tid); CP_COMMIT();

        for (int kt = 0; kt < NCH; kt++){
            if (kt < NCH - 1) CP_WAIT(1); else CP_WAIT(0);
            __syncthreads();   // S_kt: chunk kt visible AND all warps done with chunk kt-1

            if (kt + 2 < NCH){
                flag_poll16(kt + 2, s, half, lane);     // all warps, no block sync
                load_chunk(abase + ((kt + 2) % 3) * CHB, hsrc, m0, kt + 2, tid);
                CP_COMMIT();
            }

            const unsigned ab = abase + (kt % 3) * CHB;
            #pragma unroll
            for (int kkl = 0; kkl < 8; kkl++){
                const int lrow = lane & 15;
                const int koff = warp_k * 128 + kkl * 16 + ((lane >> 4) << 3);
                const int c16  = koff >> 3;
                unsigned ah[2][4];
                #pragma unroll
                for (int mt = 0; mt < 2; mt++){
                    int r = warp_m * 32 + mt * 16 + lrow;
                    ldmx4(ah[mt], ab + r * 512 + ((((c16 ^ r) & 7) | (c16 & 24)) << 4));
                }
                #pragma unroll
                for (int bn = 0; bn < 2; bn++){
                    int r = warp_n * 32 + bn * 16 + lrow;
                    int c8 = (kt * 256 + koff) >> 3;
                    unsigned t4[4], b[2][2];
                    ldmx4(t4, wbase + r * 2048 + (((c8 & ~7) | ((c8 ^ r) & 7)) << 4));
                    b[0][0] = t4[0]; b[1][0] = t4[1]; b[0][1] = t4[2]; b[1][1] = t4[3];
                    #pragma unroll
                    for (int mt = 0; mt < 2; mt++)
                        #pragma unroll
                        for (int nt = 0; nt < 2; nt++)
                            mma_f16(acc[mt][bn * 2 + nt], ah[mt], b[nt]);
                }
            }
        }
        __syncthreads();           // all compute done before gates overwrite stage 0

        // stage gate partials: warp_k==0 -> buffer 0, warp_k==1 -> buffer 1
        float* gates = (float*)(dyn + OFF_A + warp_k * 16384);
        #pragma unroll
        for (int mt = 0; mt < 2; mt++)
            #pragma unroll
            for (int bn = 0; bn < 2; bn++)
                #pragma unroll
                for (int nt = 0; nt < 2; nt++)
                    #pragma unroll
                    for (int pp = 0; pp < 2; pp++){
                        int row = warp_m * 32 + mt * 16 + (lane >> 2) + 8 * pp;
                        int col = warp_n * 32 + bn * 16 + nt * 8 + 2 * (lane & 3);
                        gates[row * 64 + col]     = acc[mt][bn * 2 + nt][2 * pp];
                        gates[row * 64 + col + 1] = acc[mt][bn * 2 + nt][2 * pp + 1];
                    }
        __syncthreads();

        {
            const float* gr0 = (const float*)(dyn + OFF_A)         + erow * 64 + q * 16;
            const float* gr1 = (const float*)(dyn + OFF_A + 16384) + erow * 64 + q * 16;
            __half hbuf[4];
            #pragma unroll
            for (int u = 0; u < 4; u++){
                float4 ga = *reinterpret_cast<const float4*>(gr0 + u * 4);
                float4 gb = *reinterpret_cast<const float4*>(gr1 + u * 4);
                const __half2* xh2 = reinterpret_cast<const __half2*>(&xpk[u >> 1]);
                float2 xa = __half22float2(xh2[(u & 1) * 2]);
                float2 xb = __half22float2(xh2[(u & 1) * 2 + 1]);
                float ig = fsig  (ga.x + gb.x + xa.x);
                float fg = fsig  (ga.y + gb.y + xa.y);
                float gg = ftanh_(ga.z + gb.z + xb.x);
                float og = fsig  (ga.w + gb.w + xb.y);
                creg[u] = fg * creg[u] + ig * gg;
                hbuf[u] = __float2half_rn(og * ftanh_(creg[u]));
            }
            *reinterpret_cast<uint2*>(&g_hh[(s + 1) & 1][grow * HID + ub]) =
                *reinterpret_cast<uint2*>(hbuf);
        }

        __threadfence();
        __syncthreads();
        if (tid == 0) *(volatile int*)&g_flag[myflag] = s + 1;
    }
}

// ---------------- decode (bank-conflict-free weights, parallel softmax) ----------------
#define WSTRD 1056                       // row stride, 1056 % 32 == 0
__device__ __forceinline__ int widx(int kk){ return kk + 4 * (kk >> 7); }

__global__ void lstm_decode(const float* __restrict__ W_dec, const float* __restrict__ b_dec,
                            float* __restrict__ out){
    __shared__ float wsh[NOUT * WSTRD];
    __shared__ float lsh[NOUT * NBATCH];
    __shared__ float red[2 * NOUT];
    int tid = threadIdx.x;
    for (int i = tid; i < NOUT * HID; i += 1024){
        int o = i >> 10, kk = i & 1023;
        wsh[o * WSTRD + widx(kk)] = W_dec[i];
    }
    __syncthreads();
    int b = tid >> 3, kseg = tid & 7;
    const uint4* hp = reinterpret_cast<const uint4*>(&g_hh[0][b * HID + kseg * 128]);
    float a[4] = {0.f, 0.f, 0.f, 0.f};
    #pragma unroll 4
    for (int v = 0; v < 16; v++){
        uint4 pk = hp[v];
        const __half* h8 = reinterpret_cast<const __half*>(&pk);
        #pragma unroll
        for (int e = 0; e < 8; e++){
            float hv = __half2float(h8[e]);
            int iw = widx(kseg * 128 + v * 8 + e);
            a[0] += hv * wsh[iw];
            a[1] += hv * wsh[WSTRD + iw];
            a[2] += hv * wsh[2 * WSTRD + iw];
            a[3] += hv * wsh[3 * WSTRD + iw];
        }
    }
    #pragma unroll
    for (int o = 0; o < 4; o++){
        a[o] += __shfl_xor_sync(0xFFFFFFFFu, a[o], 1);
        a[o] += __shfl_xor_sync(0xFFFFFFFFu, a[o], 2);
        a[o] += __shfl_xor_sync(0xFFFFFFFFu, a[o], 4);
    }
    if (kseg == 0){
        #pragma unroll
        for (int o = 0; o < 4; o++) lsh[o * NBATCH + b] = a[o] + b_dec[o];
    }
    __syncthreads();
    // warp o (o<4): parallel max/sum over the 128-batch with shfl reductions
    if (tid < 128){
        int o = tid >> 5, l = tid & 31;
        float m = -1e30f;
        #pragma unroll
        for (int j = 0; j < 4; j++) m = fmaxf(m, lsh[o * NBATCH + l + j * 32]);
        #pragma unroll
        for (int d = 16; d > 0; d >>= 1) m = fmaxf(m, __shfl_xor_sync(0xFFFFFFFFu, m, d));
        float sum = 0.0f;
        #pragma unroll
        for (int j = 0; j < 4; j++) sum += expf(lsh[o * NBATCH + l + j * 32] - m);
        #pragma unroll
        for (int d = 16; d > 0; d >>= 1) sum += __shfl_xor_sync(0xFFFFFFFFu, sum, d);
        if (l == 0){ red[o] = m; red[NOUT + o] = sum; }
    }
    __syncthreads();
    if (tid < NBATCH){
        #pragma unroll
        for (int o = 0; o < NOUT; o++)
            out[tid * NOUT + o] = expf(lsh[o * NBATCH + tid] - red[o]) / red[NOUT + o];
    }
}

// ---------------- launch ----------------
extern "C" void kernel_launch(void* const* d_in, const int* in_sizes, int n_in,
                              void* d_out, int out_size)
{
    const float* inputs = (const float*)d_in[0];
    const float* h0     = (const float*)d_in[1];
    const float* c0     = (const float*)d_in[2];
    const float* W_ih   = (const float*)d_in[3];
    const float* W_hh   = (const float*)d_in[4];
    const float* b_ih   = (const float*)d_in[5];
    const float* b_hh   = (const float*)d_in[6];
    const float* W_dec  = (const float*)d_in[7];
    const float* b_dec  = (const float*)d_in[8];
    float* out = (float*)d_out;

    cudaFuncSetAttribute(lstm_rec, cudaFuncAttributeMaxDynamicSharedMemorySize, DYN_B);
    cudaFuncSetAttribute(xproj_gemm, cudaFuncAttributeMaxDynamicSharedMemorySize, P1DYN);

    {
        int n8 = (S_LEN * NBATCH * IN_DIM) / 8;
        cvt_inputs<<<(n8 + 255) / 256, 256>>>(inputs);
        int nw = GDIM * (IN_DIM / 4);
        cvt_wih<<<(nw + 255) / 256, 256>>>(W_ih, b_ih, b_hh, h0);
    }

    dim3 g1(GDIM / BN, (S_LEN * NBATCH) / BM);   // 32 x 512
    xproj_gemm<<<g1, P1TH, P1DYN>>>();

    lstm_rec<<<PGRID, PTH, DYN_B>>>(W_hh, c0);

    lstm_decode<<<1, 1024>>>(W_dec, b_dec, out);
}

// round 16
// speedup vs baseline: 1.0173x; 1.0173x over previous
#include <cuda_runtime.h>
#include <cuda_bf16.h>
#include <cuda_fp16.h>
#include <math.h>
#include <stdint.h>

#define S_LEN   512
#define NBATCH  128
#define IN_DIM  512
#define HID     1024
#define GDIM    4096   // interleaved: col g -> gate g&3, unit g>>2
#define NOUT    4

// phase-1 tiling: 128x128 tiles, BK=64, 3-stage cp.async (R11-proven)
#define BM 128
#define BN 128
#define BKP 64
#define P1TH 256
#define P1STG_B 32768
#define P1DYN (3 * P1STG_B)

// recurrence: 128 CTAs = 2 row-halves x 64 col-tiles, each 64x64xK
// 8 warps = 2(m) x 2(n) x 2(k-split): 32x32 tiles (R14-proven)
#define PGRID 128
#define PTH 256
#define NCH 4                    // K chunks of 256
#define CHB 32768                // chunk: 64 rows x 512B
#define WB  131072               // W: 64 gate-cols x 2048B
#define OFF_W 0
#define OFF_A WB
#define DYN_B (WB + 3 * CHB)     // 229376

__device__ __half g_xp[(size_t)S_LEN * NBATCH * GDIM];   // x_proj (+bias), fp16
__device__ __half g_xh[(size_t)S_LEN * NBATCH * IN_DIM]; // inputs fp16
__device__ __half g_wih[(size_t)GDIM * IN_DIM];          // gathered W_ih fp16
__device__ float  g_bias[GDIM];                          // gathered b_ih+b_hh
__device__ __half g_hh[2][NBATCH * HID];                 // hidden fp16, dbl-buffered
__device__ int g_flag[PGRID * 32];                       // per-CTA step flag, 1 line each

__device__ __forceinline__ unsigned su32(const void* p){
    return (unsigned)__cvta_generic_to_shared(p);
}
__device__ __forceinline__ float fsig(float x){
    float e, r;
    asm("ex2.approx.f32 %0, %1;" : "=f"(e) : "f"(-x * 1.4426950408889634f));
    asm("rcp.approx.f32 %0, %1;" : "=f"(r) : "f"(1.0f + e));
    return r;
}
__device__ __forceinline__ float ftanh_(float x){
    float r;
    asm("tanh.approx.f32 %0, %1;" : "=f"(r) : "f"(x));
    return r;
}
__device__ __forceinline__ void cpasync16(unsigned saddr, const void* g){
    asm volatile("cp.async.cg.shared.global [%0], [%1], 16;" :: "r"(saddr), "l"(g));
}
#define CP_COMMIT() asm volatile("cp.async.commit_group;")
#define CP_WAIT(n)  asm volatile("cp.async.wait_group %0;" :: "n"(n))

__device__ __forceinline__ void ldmx4(unsigned* r, unsigned addr){
    asm volatile("ldmatrix.sync.aligned.m8n8.x4.shared.b16 {%0,%1,%2,%3}, [%4];"
        : "=r"(r[0]), "=r"(r[1]), "=r"(r[2]), "=r"(r[3]) : "r"(addr));
}
__device__ __forceinline__ void mma_f16(float* d, const unsigned* a, const unsigned* b){
    asm volatile("mma.sync.aligned.m16n8k16.row.col.f32.f16.f16.f32 "
        "{%0,%1,%2,%3},{%4,%5,%6,%7},{%8,%9},{%0,%1,%2,%3};"
        : "+f"(d[0]), "+f"(d[1]), "+f"(d[2]), "+f"(d[3])
        : "r"(a[0]), "r"(a[1]), "r"(a[2]), "r"(a[3]), "r"(b[0]), "r"(b[1]));
}

// warp-0 poll: chunk ch of the caller's half needs col-tiles [16ch,16ch+16) at flag >= tgt
__device__ __forceinline__ void flag_poll16(int ch, int tgt, int half, int lane){
    if (lane < 16){
        const volatile int* f = &g_flag[(((ch << 4) + lane) * 2 + half) * 32];
        while (*f < tgt) __nanosleep(64);
    }
    __syncwarp();
}

// ---------------- conversion pre-kernels ----------------
__global__ void cvt_inputs(const float* __restrict__ in){
    size_t i = (size_t)(blockIdx.x * blockDim.x + threadIdx.x) * 8;
    if (i < (size_t)S_LEN * NBATCH * IN_DIM){
        float4 v0 = *reinterpret_cast<const float4*>(in + i);
        float4 v1 = *reinterpret_cast<const float4*>(in + i + 4);
        __half2* d = reinterpret_cast<__half2*>(&g_xh[i]);
        d[0] = __floats2half2_rn(v0.x, v0.y);
        d[1] = __floats2half2_rn(v0.z, v0.w);
        d[2] = __floats2half2_rn(v1.x, v1.y);
        d[3] = __floats2half2_rn(v1.z, v1.w);
    }
}
__global__ void cvt_wih(const float* __restrict__ W_ih,
                        const float* __restrict__ b_ih, const float* __restrict__ b_hh,
                        const float* __restrict__ h0){
    int idx = blockIdx.x * blockDim.x + threadIdx.x;
    if (idx < GDIM * (IN_DIM / 4)){
        int g = idx >> 7;
        int c = (idx & 127) * 4;
        int r = (g & 3) * HID + (g >> 2);
        float4 v = *reinterpret_cast<const float4*>(W_ih + (size_t)r * IN_DIM + c);
        __half2* d = reinterpret_cast<__half2*>(&g_wih[(size_t)g * IN_DIM + c]);
        d[0] = __floats2half2_rn(v.x, v.y);
        d[1] = __floats2half2_rn(v.z, v.w);
        if (c == 0) g_bias[g] = b_ih[r] + b_hh[r];
    }
    if (idx < NBATCH * HID) g_hh[0][idx] = __float2half_rn(h0[idx]);
    if (idx < PGRID) g_flag[idx * 32] = 0;
}

// ---------------- phase 1: x_proj 128x128, 3-stage cp.async (R11-proven) ----------------
__global__ __launch_bounds__(P1TH)
void xproj_gemm()
{
    extern __shared__ __align__(1024) char p1s[];
    const int tid = threadIdx.x, lane = tid & 31, wid = tid >> 5;
    const int warp_m = wid & 3;
    const int warp_n = wid >> 2;
    const int m0 = blockIdx.y * BM, n0 = blockIdx.x * BN;
    const unsigned sbase = su32(p1s);

    float acc[2][4][2][4];
    #pragma unroll
    for (int a = 0; a < 2; a++)
        #pragma unroll
        for (int b = 0; b < 4; b++)
            #pragma unroll
            for (int c = 0; c < 2; c++)
                #pragma unroll
                for (int d = 0; d < 4; d++) acc[a][b][c][d] = 0.0f;

    int pr[8], pc[8], ppart[8];
    const __half* gsrc[8];
    #pragma unroll
    for (int i = 0; i < 8; i++){
        int idx = tid + i * P1TH;
        ppart[i] = idx >> 10;
        int w = idx & 1023;
        pr[i] = w >> 3;
        pc[i] = w & 7;
        gsrc[i] = ppart[i] ? (g_wih + (size_t)(n0 + pr[i]) * IN_DIM + pc[i] * 8)
                           : (g_xh  + (size_t)(m0 + pr[i]) * IN_DIM + pc[i] * 8);
    }

    #pragma unroll
    for (int st = 0; st < 2; st++){
        #pragma unroll
        for (int i = 0; i < 8; i++){
            unsigned dst = sbase + st * P1STG_B + ppart[i] * 16384
                         + pr[i] * 128 + ((pc[i] ^ (pr[i] & 7)) << 4);
            cpasync16(dst, gsrc[i] + st * BKP);
        }
        CP_COMMIT();
    }

    const int KIT = IN_DIM / BKP;
    for (int kt = 0; kt < KIT; kt++){
        if (kt + 1 < KIT) CP_WAIT(1); else CP_WAIT(0);
        __syncthreads();

        if (kt + 2 < KIT){
            int st = (kt + 2) % 3;
            #pragma unroll
            for (int i = 0; i < 8; i++){
                unsigned dst = sbase + st * P1STG_B + ppart[i] * 16384
                             + pr[i] * 128 + ((pc[i] ^ (pr[i] & 7)) << 4);
                cpasync16(dst, gsrc[i] + (kt + 2) * BKP);
            }
            CP_COMMIT();
        }

        const unsigned ab = sbase + (kt % 3) * P1STG_B;
        const unsigned bb = ab + 16384;
        #pragma unroll
        for (int kk = 0; kk < 4; kk++){
            const int lrow = lane & 15;
            const int cc = (kk * 16 + ((lane >> 4) << 3)) >> 3;
            unsigned ah[2][4];
            #pragma unroll
            for (int mt = 0; mt < 2; mt++){
                int r = warp_m * 32 + mt * 16 + lrow;
                ldmx4(ah[mt], ab + r * 128 + ((cc ^ (r & 7)) << 4));
            }
            #pragma unroll
            for (int nb = 0; nb < 4; nb++){
                int r = warp_n * 64 + nb * 16 + lrow;
                unsigned t4[4], b[2][2];
                ldmx4(t4, bb + r * 128 + ((cc ^ (r & 7)) << 4));
                b[0][0] = t4[0]; b[1][0] = t4[1]; b[0][1] = t4[2]; b[1][1] = t4[3];
                #pragma unroll
                for (int mt = 0; mt < 2; mt++)
                    #pragma unroll
                    for (int nt = 0; nt < 2; nt++)
                        mma_f16(acc[mt][nb][nt], ah[mt], b[nt]);
            }
        }
    }

    #pragma unroll
    for (int mt = 0; mt < 2; mt++)
        #pragma unroll
        for (int nb = 0; nb < 4; nb++)
            #pragma unroll
            for (int nt = 0; nt < 2; nt++)
                #pragma unroll
                for (int pp = 0; pp < 2; pp++){
                    int row = m0 + warp_m * 32 + mt * 16 + (lane >> 2) + 8 * pp;
                    int col = n0 + warp_n * 64 + nb * 16 + nt * 8 + 2 * (lane & 3);
                    float v0 = acc[mt][nb][nt][2 * pp]     + g_bias[col];
                    float v1 = acc[mt][nb][nt][2 * pp + 1] + g_bias[col + 1];
                    *reinterpret_cast<__half2*>(&g_xp[(size_t)row * GDIM + col]) =
                        __floats2half2_rn(v0, v1);
                }
}

// ---------------- persistent recurrence (exact R14 form) ----------------
__device__ __forceinline__ void load_chunk(unsigned abase_st, const __half* hsrc,
                                           int m0, int kt, int tid){
    #pragma unroll
    for (int i = 0; i < 8; i++){
        int u = tid + i * PTH;
        int r = u >> 5;
        int c16 = u & 31;
        const __half* src = hsrc + (size_t)(m0 + r) * HID + kt * 256 + c16 * 8;
        unsigned dst = abase_st + r * 512 + ((((c16 ^ r) & 7) | (c16 & 24)) << 4);
        cpasync16(dst, src);
    }
}

__global__ __launch_bounds__(PTH, 1)
void lstm_rec(const float* __restrict__ W_hh, const float* __restrict__ c0)
{
    extern __shared__ __align__(1024) char dyn[];
    const int tid  = threadIdx.x;
    const int lane = tid & 31;
    const int wid  = tid >> 5;
    const int warp_m = wid & 1;          // 0..1 : 32 rows
    const int warp_n = (wid >> 1) & 1;   // 0..1 : 32 cols
    const int warp_k = wid >> 2;         // 0..1 : K half of each chunk
    const int half = blockIdx.x & 1;
    const int m0 = half * 64;
    const int n0 = (blockIdx.x >> 1) * 64;
    const int myflag = blockIdx.x * 32;
    const unsigned wbase = su32(dyn + OFF_W);
    const unsigned abase = su32(dyn + OFF_A);

    for (int idx = tid; idx < 64 * (HID / 8); idx += PTH){
        int j  = idx >> 7;
        int c8 = idx & 127;
        int c  = c8 * 8;
        int g  = n0 + j;
        const float* src = W_hh + (size_t)((g & 3) * HID + (g >> 2)) * HID + c;
        float4 v0 = *reinterpret_cast<const float4*>(src);
        float4 v1 = *reinterpret_cast<const float4*>(src + 4);
        int sc = (c8 & ~7) | ((c8 ^ j) & 7);
        __half2* d = reinterpret_cast<__half2*>(dyn + OFF_W + j * 2048 + (sc << 4));
        d[0] = __floats2half2_rn(v0.x, v0.y);
        d[1] = __floats2half2_rn(v0.z, v0.w);
        d[2] = __floats2half2_rn(v1.x, v1.y);
        d[3] = __floats2half2_rn(v1.z, v1.w);
    }

    // epilogue ownership: 256 threads, each 4 consecutive units of one row
    const int erow = tid >> 2;               // 0..63 local batch row
    const int q    = tid & 3;                // quarter of the 16 units
    const int grow = m0 + erow;
    const int ub   = (n0 >> 2) + q * 4;      // first unit (4 per thread)
    float creg[4];
    #pragma unroll
    for (int u = 0; u < 4; u++) creg[u] = c0[grow * HID + ub + u];
    __syncthreads();

    for (int s = 0; s < S_LEN; s++){
        const __half* hsrc = g_hh[s & 1];

        // prefetch x_proj segment (16 fp16 = 2 uint4)
        const __half* xpr = g_xp + ((size_t)s * NBATCH + grow) * GDIM + n0 + q * 16;
        uint4 xpk[2];
        xpk[0] = *reinterpret_cast<const uint4*>(xpr);
        xpk[1] = *reinterpret_cast<const uint4*>(xpr + 8);

        float acc[2][4][4];   // [mt][bn*2+nt][4] (partial over this warp's K half)
        #pragma unroll
        for (int a = 0; a < 2; a++)
            #pragma unroll
            for (int b = 0; b < 4; b++)
                #pragma unroll
                for (int k = 0; k < 4; k++) acc[a][b][k] = 0.0f;

        // wait for chunk 0+1 producers (col-tiles 0..31 of this half), then load
        if (wid == 0 && lane < 32){
            const volatile int* f = &g_flag[(lane * 2 + half) * 32];
            while (*f < s) __nanosleep(64);
        }
        __syncthreads();
        load_chunk(abase + 0 * CHB, hsrc, m0, 0, tid); CP_COMMIT();
        load_chunk(abase + 1 * CHB, hsrc, m0, 1, tid); CP_COMMIT();

        for (int kt = 0; kt < NCH; kt++){
            if (kt + 2 < NCH){
                if (wid == 0) flag_poll16(kt + 2, s, half, lane);
                __syncthreads();
                load_chunk(abase + ((kt + 2) % 3) * CHB, hsrc, m0, kt + 2, tid);
                CP_COMMIT();
                CP_WAIT(2);
            } else if (kt == NCH - 2){
                CP_WAIT(1);
            } else {
                CP_WAIT(0);
            }
            __syncthreads();

            const unsigned ab = abase + (kt % 3) * CHB;
            #pragma unroll
            for (int kkl = 0; kkl < 8; kkl++){
                const int lrow = lane & 15;
                const int koff = warp_k * 128 + kkl * 16 + ((lane >> 4) << 3);
                const int c16  = koff >> 3;
                unsigned ah[2][4];
                #pragma unroll
                for (int mt = 0; mt < 2; mt++){
                    int r = warp_m * 32 + mt * 16 + lrow;
                    ldmx4(ah[mt], ab + r * 512 + ((((c16 ^ r) & 7) | (c16 & 24)) << 4));
                }
                #pragma unroll
                for (int bn = 0; bn < 2; bn++){
                    int r = warp_n * 32 + bn * 16 + lrow;
                    int c8 = (kt * 256 + koff) >> 3;
                    unsigned t4[4], b[2][2];
                    ldmx4(t4, wbase + r * 2048 + (((c8 & ~7) | ((c8 ^ r) & 7)) << 4));
                    b[0][0] = t4[0]; b[1][0] = t4[1]; b[0][1] = t4[2]; b[1][1] = t4[3];
                    #pragma unroll
                    for (int mt = 0; mt < 2; mt++)
                        #pragma unroll
                        for (int nt = 0; nt < 2; nt++)
                            mma_f16(acc[mt][bn * 2 + nt], ah[mt], b[nt]);
                }
            }
        }
        __syncthreads();           // all compute done before gates overwrite stage 0

        // stage gate partials: warp_k==0 -> buffer 0, warp_k==1 -> buffer 1 (32KB total)
        float* gates = (float*)(dyn + OFF_A + warp_k * 16384);
        #pragma unroll
        for (int mt = 0; mt < 2; mt++)
            #pragma unroll
            for (int bn = 0; bn < 2; bn++)
                #pragma unroll
                for (int nt = 0; nt < 2; nt++)
                    #pragma unroll
                    for (int pp = 0; pp < 2; pp++){
                        int row = warp_m * 32 + mt * 16 + (lane >> 2) + 8 * pp;
                        int col = warp_n * 32 + bn * 16 + nt * 8 + 2 * (lane & 3);
                        gates[row * 64 + col]     = acc[mt][bn * 2 + nt][2 * pp];
                        gates[row * 64 + col + 1] = acc[mt][bn * 2 + nt][2 * pp + 1];
                    }
        __syncthreads();

        {
            const float* gr0 = (const float*)(dyn + OFF_A)         + erow * 64 + q * 16;
            const float* gr1 = (const float*)(dyn + OFF_A + 16384) + erow * 64 + q * 16;
            __half hbuf[4];
            #pragma unroll
            for (int u = 0; u < 4; u++){
                float4 ga = *reinterpret_cast<const float4*>(gr0 + u * 4);
                float4 gb = *reinterpret_cast<const float4*>(gr1 + u * 4);
                const __half2* xh2 = reinterpret_cast<const __half2*>(&xpk[u >> 1]);
                float2 xa = __half22float2(xh2[(u & 1) * 2]);
                float2 xb = __half22float2(xh2[(u & 1) * 2 + 1]);
                float ig = fsig  (ga.x + gb.x + xa.x);
                float fg = fsig  (ga.y + gb.y + xa.y);
                float gg = ftanh_(ga.z + gb.z + xb.x);
                float og = fsig  (ga.w + gb.w + xb.y);
                creg[u] = fg * creg[u] + ig * gg;
                hbuf[u] = __float2half_rn(og * ftanh_(creg[u]));
            }
            *reinterpret_cast<uint2*>(&g_hh[(s + 1) & 1][grow * HID + ub]) =
                *reinterpret_cast<uint2*>(hbuf);
        }

        // publish: h stores fenced, then block sync, then single flag store
        __threadfence();
        __syncthreads();
        if (tid == 0) *(volatile int*)&g_flag[myflag] = s + 1;
    }
}

// ---------------- decode (bank-conflict-free weights, parallel softmax) ----------------
#define WSTRD 1056                       // padded row stride
__device__ __forceinline__ int widx(int kk){ return kk + 4 * (kk >> 7); }

__global__ void lstm_decode(const float* __restrict__ W_dec, const float* __restrict__ b_dec,
                            float* __restrict__ out){
    __shared__ float wsh[NOUT * WSTRD];
    __shared__ float lsh[NOUT * NBATCH];
    __shared__ float red[2 * NOUT];
    int tid = threadIdx.x;
    for (int i = tid; i < NOUT * HID; i += 1024){
        int o = i >> 10, kk = i & 1023;
        wsh[o * WSTRD + widx(kk)] = W_dec[i];
    }
    __syncthreads();
    int b = tid >> 3, kseg = tid & 7;
    const uint4* hp = reinterpret_cast<const uint4*>(&g_hh[0][b * HID + kseg * 128]);
    float a[4] = {0.f, 0.f, 0.f, 0.f};
    #pragma unroll 4
    for (int v = 0; v < 16; v++){
        uint4 pk = hp[v];
        const __half* h8 = reinterpret_cast<const __half*>(&pk);
        #pragma unroll
        for (int e = 0; e < 8; e++){
            float hv = __half2float(h8[e]);
            int iw = widx(kseg * 128 + v * 8 + e);
            a[0] += hv * wsh[iw];
            a[1] += hv * wsh[WSTRD + iw];
            a[2] += hv * wsh[2 * WSTRD + iw];
            a[3] += hv * wsh[3 * WSTRD + iw];
        }
    }
    #pragma unroll
    for (int o = 0; o < 4; o++){
        a[o] += __shfl_xor_sync(0xFFFFFFFFu, a[o], 1);
        a[o] += __shfl_xor_sync(0xFFFFFFFFu, a[o], 2);
        a[o] += __shfl_xor_sync(0xFFFFFFFFu, a[o], 4);
    }
    if (kseg == 0){
        #pragma unroll
        for (int o = 0; o < 4; o++) lsh[o * NBATCH + b] = a[o] + b_dec[o];
    }
    __syncthreads();
    // warp o (o<4): parallel max/sum over the 128-batch with shfl reductions
    if (tid < 128){
        int o = tid >> 5, l = tid & 31;
        float m = -1e30f;
        #pragma unroll
        for (int j = 0; j < 4; j++) m = fmaxf(m, lsh[o * NBATCH + l + j * 32]);
        #pragma unroll
        for (int d = 16; d > 0; d >>= 1) m = fmaxf(m, __shfl_xor_sync(0xFFFFFFFFu, m, d));
        float sum = 0.0f;
        #pragma unroll
        for (int j = 0; j < 4; j++) sum += expf(lsh[o * NBATCH + l + j * 32] - m);
        #pragma unroll
        for (int d = 16; d > 0; d >>= 1) sum += __shfl_xor_sync(0xFFFFFFFFu, sum, d);
        if (l == 0){ red[o] = m; red[NOUT + o] = sum; }
    }
    __syncthreads();
    if (tid < NBATCH){
        #pragma unroll
        for (int o = 0; o < NOUT; o++)
            out[tid * NOUT + o] = expf(lsh[o * NBATCH + tid] - red[o]) / red[NOUT + o];
    }
}

// ---------------- launch ----------------
extern "C" void kernel_launch(void* const* d_in, const int* in_sizes, int n_in,
                              void* d_out, int out_size)
{
    const float* inputs = (const float*)d_in[0];
    const float* h0     = (const float*)d_in[1];
    const float* c0     = (const float*)d_in[2];
    const float* W_ih   = (const float*)d_in[3];
    const float* W_hh   = (const float*)d_in[4];
    const float* b_ih   = (const float*)d_in[5];
    const float* b_hh   = (const float*)d_in[6];
    const float* W_dec  = (const float*)d_in[7];
    const float* b_dec  = (const float*)d_in[8];
    float* out = (float*)d_out;

    cudaFuncSetAttribute(lstm_rec, cudaFuncAttributeMaxDynamicSharedMemorySize, DYN_B);
    cudaFuncSetAttribute(xproj_gemm, cudaFuncAttributeMaxDynamicSharedMemorySize, P1DYN);

    {
        int n8 = (S_LEN * NBATCH * IN_DIM) / 8;
        cvt_inputs<<<(n8 + 255) / 256, 256>>>(inputs);
        int nw = GDIM * (IN_DIM / 4);
        cvt_wih<<<(nw + 255) / 256, 256>>>(W_ih, b_ih, b_hh, h0);
    }

    dim3 g1(GDIM / BN, (S_LEN * NBATCH) / BM);   // 32 x 512
    xproj_gemm<<<g1, P1TH, P1DYN>>>();

    lstm_rec<<<PGRID, PTH, DYN_B>>>(W_hh, c0);

    lstm_decode<<<1, 1024>>>(W_dec, b_dec, out);
}